// round 17
// baseline (speedup 1.0000x reference)
#include <cuda_runtime.h>

// out[b,:] = (cnt>0) ? sum_c w[b,c] * F[i0(b,c),:] * F[i1(b,c),:]  :  F[b,:]
// D = 128. One warp per target; lane owns a float4 (two f32x2 pairs).
// Geometry: 148 blocks x 1024 thr, contiguous chunk/block, warp work-stealing.
//
// Metadata staged to SMEM at block start as 8-byte records (w, i0|i1<<16),
// per-target counts precomputed. Inner loop reads one combo-PAIR per LDS.128
// (warp-uniform broadcast) and runs a counted loop — no ballot, no shuffles,
// no data-dependent break in the hot path.
// Kept from champion: row-reuse chain (self/square/adjacent), f32x2 FMA.
// (Resubmission: R16 bench was an infra failure; static-guard around
//  cudaFuncSetAttribute removed for harness compliance.)

#define THREADS 1024
#define NSM 148
#define FULL 0xffffffffu

__device__ __forceinline__ unsigned long long pack2(float x) {
    unsigned long long r;
    asm("mov.b64 %0, {%1, %1};" : "=l"(r) : "f"(x));
    return r;
}
__device__ __forceinline__ unsigned long long mul2(unsigned long long a,
                                                   unsigned long long b) {
    unsigned long long d;
    asm("mul.rn.f32x2 %0, %1, %2;" : "=l"(d) : "l"(a), "l"(b));
    return d;
}
__device__ __forceinline__ unsigned long long fma2(unsigned long long a,
                                                   unsigned long long b,
                                                   unsigned long long c) {
    unsigned long long d;
    asm("fma.rn.f32x2 %0, %1, %2, %3;" : "=l"(d) : "l"(a), "l"(b), "l"(c));
    return d;
}

__global__ __launch_bounds__(THREADS, 1)
void tmp_kernel(const float* __restrict__ features,
                const int2*  __restrict__ comb_idx,   // [B, C] int2 pairs
                const float* __restrict__ comb_w,     // [B, C]
                float*       __restrict__ out,        // [B, 128]
                int B, int C, int chunk)
{
    extern __shared__ uint2 meta[];   // [nt][Cp] records: (w_bits, i0|i1<<16)
    __shared__ int s_cnt[512];
    __shared__ int s_ctr;

    const int tid  = threadIdx.x;
    const int lane = tid & 31;
    const int start = blockIdx.x * chunk;
    if (start >= B) return;
    const int nt = min(chunk, B - start);
    const int Cp = (C + 1) & ~1;          // even stride -> 16B-aligned pairs

    if (tid == 0) s_ctr = 0;
    for (int i = tid; i < nt; i += THREADS) s_cnt[i] = 0;
    __syncthreads();

    // ---- stage metadata (coalesced) + count nonzero weights per target ----
    for (int idx = tid; idx < nt * Cp; idx += THREADS) {
        const int t = idx / Cp;
        const int c = idx - t * Cp;
        uint2 rec = make_uint2(0u, 0u);
        if (c < C) {
            const long g = (long)(start + t) * C + c;
            const float w = __ldg(comb_w + g);
            if (w != 0.0f) {
                const int2 p = __ldg(comb_idx + g);
                rec.x = __float_as_uint(w);
                rec.y = (unsigned)p.x | ((unsigned)p.y << 16);  // N < 65536
                atomicAdd(&s_cnt[t], 1);
            }
        }
        meta[t * Cp + c] = rec;
    }
    __syncthreads();

    const ulonglong2* __restrict__ f2 =
        reinterpret_cast<const ulonglong2*>(features);   // row = 32 x ulonglong2

    for (;;) {
        // ---- steal next target (warp-uniform) ----
        int t = 0;
        if (lane == 0) t = atomicAdd(&s_ctr, 1);
        t = __shfl_sync(FULL, t, 0);
        if (t >= nt) break;
        const int b = start + t;

        const ulonglong2 self = __ldg(f2 + (long)b * 32 + lane);
        unsigned long long acc01 = 0, acc23 = 0;

        const int cnt = s_cnt[t];
        const int pairs = (cnt + 1) >> 1;     // odd tail: record has w=0 -> adds 0
        const uint4* __restrict__ recs =
            reinterpret_cast<const uint4*>(meta + t * Cp);

        for (int j = 0; j < pairs; ++j) {
            const uint4 r = recs[j];          // one LDS.128: (w0,pk0,w1,pk1)
            const float    w0  = __uint_as_float(r.x);
            const unsigned pk0 = r.y;
            const float    w1  = __uint_as_float(r.z);
            const unsigned pk1 = r.w;

            const int i00 = (int)(pk0 & 0xFFFFu);
            const int i01 = (int)(pk0 >> 16);
            const int i10 = (int)(pk1 & 0xFFFFu);
            const int i11 = (int)(pk1 >> 16);

            // reuse chain (warp-uniform predicated loads)
            ulonglong2 a0 = self;
            if (i00 != b) a0 = __ldg(f2 + (long)i00 * 32 + lane);

            ulonglong2 v0 = (i01 == b) ? self : a0;     // a0 covers i01==i00
            if (i01 != i00 && i01 != b)
                v0 = __ldg(f2 + (long)i01 * 32 + lane);

            ulonglong2 a1 = (i10 == b) ? self : v0;     // v0 covers i10==i01
            if (i10 != i01 && i10 != b)
                a1 = __ldg(f2 + (long)i10 * 32 + lane);

            ulonglong2 v1 = a1;                          // covers i11==i10
            if (i11 != i10)
                v1 = __ldg(f2 + (long)i11 * 32 + lane);

            const unsigned long long w0p = pack2(w0);
            const unsigned long long w1p = pack2(w1);

            acc01 = fma2(mul2(a0.x, w0p), v0.x, acc01);
            acc23 = fma2(mul2(a0.y, w0p), v0.y, acc23);
            acc01 = fma2(mul2(a1.x, w1p), v1.x, acc01);
            acc23 = fma2(mul2(a1.y, w1p), v1.y, acc23);
        }

        ulonglong2 rr;
        rr.x = acc01; rr.y = acc23;
        if (cnt == 0) rr = self;              // self-feature fallback (cached)
        reinterpret_cast<ulonglong2*>(out)[(long)b * 32 + lane] = rr;
    }
}

extern "C" void kernel_launch(void* const* d_in, const int* in_sizes, int n_in,
                              void* d_out, int out_size)
{
    const float* features = (const float*)d_in[0];
    // d_in[1] = target_nodes (== arange(B)); unused.
    const int2*  comb_idx = (const int2*)d_in[2];
    const float* comb_w   = (const float*)d_in[3];
    float* out = (float*)d_out;

    const int B = in_sizes[4];            // has_edge element count
    const int C = in_sizes[3] / B;        // comb_w is [B, C]

    const int chunk = (B + NSM - 1) / NSM;          // contiguous targets / block
    const int blocks = (B + chunk - 1) / chunk;     // == 148
    const int Cp = (C + 1) & ~1;
    const size_t smem = (size_t)chunk * Cp * sizeof(uint2);

    cudaFuncSetAttribute(tmp_kernel,
                         cudaFuncAttributeMaxDynamicSharedMemorySize,
                         (int)smem);

    tmp_kernel<<<blocks, THREADS, smem>>>(features, comb_idx, comb_w, out,
                                          B, C, chunk);
}